// round 1
// baseline (speedup 1.0000x reference)
#include <cuda_runtime.h>
#include <cstdint>
#include <math.h>

#define B_DIM 64
#define S_DIM 2048
#define D_DIM 512

#define BLK_S 128
#define BLK_K 32
#define LDK 36            // BLK_K + 4 pad -> conflict-free fragment loads
#define NTHREADS 256
#define NK_TILES (D_DIM / BLK_K)   // 16

// scratch for q = query @ Wq_w.T + Wq_b  (no device mallocs allowed)
__device__ float g_q[B_DIM * D_DIM];

// ---------------------------------------------------------------------------
// Kernel 1: q projection (tiny: 64 x 512 outputs)
// ---------------------------------------------------------------------------
__global__ void qproj_kernel(const float* __restrict__ query,
                             const float* __restrict__ Wq_w,
                             const float* __restrict__ Wq_b) {
    __shared__ float qs[D_DIM];
    const int b = blockIdx.x;
    for (int i = threadIdx.x; i < D_DIM; i += blockDim.x)
        qs[i] = query[(size_t)b * D_DIM + i];
    __syncthreads();
    for (int e = threadIdx.x; e < D_DIM; e += blockDim.x) {
        const float* w = Wq_w + (size_t)e * D_DIM;
        float s0 = 0.f, s1 = 0.f, s2 = 0.f, s3 = 0.f;
        #pragma unroll 4
        for (int d = 0; d < D_DIM; d += 4) {
            s0 += qs[d + 0] * w[d + 0];
            s1 += qs[d + 1] * w[d + 1];
            s2 += qs[d + 2] * w[d + 2];
            s3 += qs[d + 3] * w[d + 3];
        }
        g_q[b * D_DIM + e] = Wq_b[e] + ((s0 + s1) + (s2 + s3));
    }
}

// ---------------------------------------------------------------------------
// Helpers
// ---------------------------------------------------------------------------
__device__ __forceinline__ unsigned f2tf(float x) {
    unsigned u;
    asm("cvt.rna.tf32.f32 %0, %1;" : "=r"(u) : "f"(x));
    return u;
}
__device__ __forceinline__ void cp16(float* dst, const float* src) {
    unsigned s = (unsigned)__cvta_generic_to_shared(dst);
    asm volatile("cp.async.cg.shared.global [%0], [%1], 16;"
                 :: "r"(s), "l"(src) : "memory");
}

// dynamic smem layout (floats):
//   A: [2][BLK_S][LDK] = 9216   | W: [2][128][LDK] = 9216
//   q: 512 | v: 512 | bias: 512 | logits: 128   -> 20096 floats = 80384 B
#define SM_A(buf, r, c) sm[((buf) * BLK_S + (r)) * LDK + (c)]
#define SM_W(buf, r, c) sm[9216 + ((buf) * 128 + (r)) * LDK + (c)]
#define SM_Q(i) sm[18432 + (i)]
#define SM_V(i) sm[18944 + (i)]
#define SM_B(i) sm[19456 + (i)]
#define SM_L(i) sm[19968 + (i)]
#define SMEM_FLOATS 20096

// ---------------------------------------------------------------------------
// Kernel 2: fused r-GEMM + tanh-logits + transposed store
//   r[b,s,e] = sum_d ref[b,s,d] * Wr_w[e,d] + Wr_b[e]
//   out_r[b,e,s] = r ; logits[b,s] = 10*tanh( sum_e tanh(q[b,e]+r)*value[e] )
// ---------------------------------------------------------------------------
__global__ void __launch_bounds__(NTHREADS, 2)
attn_main(const float* __restrict__ ref,
          const float* __restrict__ Wr_w,
          const float* __restrict__ Wr_b,
          const float* __restrict__ value,
          float* __restrict__ out_r,
          float* __restrict__ out_logits)
{
    extern __shared__ float sm[];
    const int tid    = threadIdx.x;
    const int lane   = tid & 31;
    const int warp   = tid >> 5;
    const int warp_s = warp & 3;   // 4 warps over S
    const int warp_e = warp >> 2;  // 2 warps over E
    const int b  = blockIdx.y;
    const int s0 = blockIdx.x * BLK_S;

    for (int i = tid; i < D_DIM; i += NTHREADS) {
        SM_Q(i) = g_q[b * D_DIM + i];
        SM_V(i) = value[i];
        SM_B(i) = Wr_b[i];
    }
    if (tid < BLK_S) SM_L(tid) = 0.0f;

    const float* aG = ref + ((size_t)b * S_DIM + s0) * D_DIM;
    float* outr_b = out_r + (size_t)b * D_DIM * S_DIM;

    for (int ei = 0; ei < 4; ei++) {
        const float* wG = Wr_w + (size_t)(ei * 128) * D_DIM;

        float acc[2][8][4];
        #pragma unroll
        for (int tm = 0; tm < 2; tm++)
            #pragma unroll
            for (int tn = 0; tn < 8; tn++)
                #pragma unroll
                for (int i = 0; i < 4; i++) acc[tm][tn][i] = 0.f;

        // prefetch k-tile 0 into buffer 0
        #pragma unroll
        for (int i = 0; i < 4; i++) {
            int v = tid + i * NTHREADS;        // 0..1023
            int row = v >> 3, c4 = (v & 7) * 4;
            cp16(&SM_A(0, row, c4), aG + (size_t)row * D_DIM + c4);
            cp16(&SM_W(0, row, c4), wG + (size_t)row * D_DIM + c4);
        }
        asm volatile("cp.async.commit_group;" ::: "memory");

        #pragma unroll 1
        for (int kt = 0; kt < NK_TILES; kt++) {
            const int cur = kt & 1;
            if (kt + 1 < NK_TILES) {
                const int k0n = (kt + 1) * BLK_K;
                #pragma unroll
                for (int i = 0; i < 4; i++) {
                    int v = tid + i * NTHREADS;
                    int row = v >> 3, c4 = (v & 7) * 4;
                    cp16(&SM_A(cur ^ 1, row, c4), aG + (size_t)row * D_DIM + k0n + c4);
                    cp16(&SM_W(cur ^ 1, row, c4), wG + (size_t)row * D_DIM + k0n + c4);
                }
                asm volatile("cp.async.commit_group;" ::: "memory");
                asm volatile("cp.async.wait_group 1;" ::: "memory");
            } else {
                asm volatile("cp.async.wait_group 0;" ::: "memory");
            }
            __syncthreads();

            #pragma unroll
            for (int ks = 0; ks < 4; ks++) {
                const int ac = ks * 8 + (lane & 3);
                const int ar = warp_s * 32 + (lane >> 2);
                unsigned af[2][4];
                #pragma unroll
                for (int tm = 0; tm < 2; tm++) {
                    af[tm][0] = f2tf(SM_A(cur, ar + tm * 16,     ac));
                    af[tm][1] = f2tf(SM_A(cur, ar + tm * 16 + 8, ac));
                    af[tm][2] = f2tf(SM_A(cur, ar + tm * 16,     ac + 4));
                    af[tm][3] = f2tf(SM_A(cur, ar + tm * 16 + 8, ac + 4));
                }
                const int br = warp_e * 64 + (lane >> 2);
                unsigned bf[8][2];
                #pragma unroll
                for (int tn = 0; tn < 8; tn++) {
                    bf[tn][0] = f2tf(SM_W(cur, br + tn * 8, ac));
                    bf[tn][1] = f2tf(SM_W(cur, br + tn * 8, ac + 4));
                }
                #pragma unroll
                for (int tm = 0; tm < 2; tm++)
                    #pragma unroll
                    for (int tn = 0; tn < 8; tn++)
                        asm volatile(
                            "mma.sync.aligned.m16n8k8.row.col.f32.tf32.tf32.f32 "
                            "{%0,%1,%2,%3}, {%4,%5,%6,%7}, {%8,%9}, {%0,%1,%2,%3};"
                            : "+f"(acc[tm][tn][0]), "+f"(acc[tm][tn][1]),
                              "+f"(acc[tm][tn][2]), "+f"(acc[tm][tn][3])
                            : "r"(af[tm][0]), "r"(af[tm][1]),
                              "r"(af[tm][2]), "r"(af[tm][3]),
                              "r"(bf[tn][0]), "r"(bf[tn][1]));
            }
            __syncthreads();
        }

        // -------- epilogue for this 128-wide E block --------
        float lp[2][2] = {{0.f, 0.f}, {0.f, 0.f}};
        const int sg0 = s0 + warp_s * 32 + (lane >> 2);
        #pragma unroll
        for (int tm = 0; tm < 2; tm++) {
            const int srow = sg0 + tm * 16;
            #pragma unroll
            for (int tn = 0; tn < 8; tn++) {
                const int e = ei * 128 + warp_e * 64 + tn * 8 + 2 * (lane & 3);
                const float b0 = SM_B(e), b1 = SM_B(e + 1);
                const float r00 = acc[tm][tn][0] + b0;
                const float r01 = acc[tm][tn][1] + b1;
                const float r10 = acc[tm][tn][2] + b0;
                const float r11 = acc[tm][tn][3] + b1;
                outr_b[(size_t)e       * S_DIM + srow]     = r00;
                outr_b[(size_t)(e + 1) * S_DIM + srow]     = r01;
                outr_b[(size_t)e       * S_DIM + srow + 8] = r10;
                outr_b[(size_t)(e + 1) * S_DIM + srow + 8] = r11;
                const float q0 = SM_Q(e), q1 = SM_Q(e + 1);
                const float v0 = SM_V(e), v1 = SM_V(e + 1);
                lp[tm][0] += tanhf(q0 + r00) * v0 + tanhf(q1 + r01) * v1;
                lp[tm][1] += tanhf(q0 + r10) * v0 + tanhf(q1 + r11) * v1;
            }
        }
        #pragma unroll
        for (int tm = 0; tm < 2; tm++)
            #pragma unroll
            for (int h = 0; h < 2; h++) {
                float v = lp[tm][h];
                v += __shfl_xor_sync(0xffffffffu, v, 1);
                v += __shfl_xor_sync(0xffffffffu, v, 2);
                if ((lane & 3) == 0)
                    atomicAdd(&SM_L(warp_s * 32 + tm * 16 + h * 8 + (lane >> 2)), v);
            }
    }

    __syncthreads();
    if (tid < BLK_S)
        out_logits[(size_t)b * S_DIM + s0 + tid] = 10.0f * tanhf(SM_L(tid));
}

// ---------------------------------------------------------------------------
// Launch
// ---------------------------------------------------------------------------
extern "C" void kernel_launch(void* const* d_in, const int* in_sizes, int n_in,
                              void* d_out, int out_size) {
    const float* query = (const float*)d_in[0];
    const float* ref   = (const float*)d_in[1];
    const float* Wq_w  = (const float*)d_in[2];
    const float* Wq_b  = (const float*)d_in[3];
    const float* Wr_w  = (const float*)d_in[4];
    const float* Wr_b  = (const float*)d_in[5];
    const float* value = (const float*)d_in[6];
    (void)in_sizes; (void)n_in; (void)out_size;

    float* out        = (float*)d_out;
    float* out_r      = out;                                   // [B, D, S]
    float* out_logits = out + (size_t)B_DIM * D_DIM * S_DIM;   // [B, S]

    qproj_kernel<<<B_DIM, 256>>>(query, Wq_w, Wq_b);

    const size_t smem = SMEM_FLOATS * sizeof(float);
    cudaFuncSetAttribute(attn_main, cudaFuncAttributeMaxDynamicSharedMemorySize,
                         (int)smem);
    dim3 grid(S_DIM / BLK_S, B_DIM);
    attn_main<<<grid, NTHREADS, smem>>>(ref, Wr_w, Wr_b, value, out_r, out_logits);
}

// round 3
// speedup vs baseline: 1.3797x; 1.3797x over previous
#include <cuda_runtime.h>
#include <cstdint>
#include <math.h>

#define B_DIM 64
#define S_DIM 2048
#define D_DIM 512

#define BLK_S 128
#define BLK_K 32
#define LDA 36            // A pad: (36*r + c) % 32 = 4r + c -> conflict-free 32-bit
#define LDB 40            // B pad: float2 stride 20 -> (20r + c) % 16 = 4r + c -> conflict-free 64-bit
#define NTHREADS 256
#define NK_TILES (D_DIM / BLK_K)   // 16

// scratch (no device mallocs allowed)
__device__ float    g_q[B_DIM * D_DIM];
__device__ uint32_t g_wtf[D_DIM * D_DIM];   // Wr_w as tf32 bits, k-permuted within 8-groups

// ---------------------------------------------------------------------------
// Kernel 0: convert Wr_w -> tf32 (rna) with k-pair permutation
//   pos(k) = (k & ~7) | ((k & 3) << 1) | ((k >> 2) & 1)   [within 8-group]
// ---------------------------------------------------------------------------
__global__ void wconv_kernel(const float* __restrict__ Wr_w) {
    int idx = blockIdx.x * blockDim.x + threadIdx.x;
    #pragma unroll
    for (int it = 0; it < 4; it++, idx += 65536) {
        const int e = idx >> 9;
        const int k = idx & 511;
        const int pos = (k & ~7) | ((k & 3) << 1) | ((k >> 2) & 1);
        unsigned u;
        asm("cvt.rna.tf32.f32 %0, %1;" : "=r"(u) : "f"(Wr_w[idx]));
        g_wtf[(e << 9) + pos] = u;
    }
}

// ---------------------------------------------------------------------------
// Kernel 1: q projection, coalesced (warp-per-output)
// ---------------------------------------------------------------------------
__global__ void qproj_kernel(const float* __restrict__ query,
                             const float* __restrict__ Wq_w,
                             const float* __restrict__ Wq_b) {
    __shared__ float qs[D_DIM];
    const int b = blockIdx.x;
    const int tid = threadIdx.x, lane = tid & 31, w = tid >> 5;
    for (int i = tid; i < D_DIM; i += 256) qs[i] = query[(size_t)b * D_DIM + i];
    __syncthreads();
    const int e0 = blockIdx.y * 32 + w * 4;
    #pragma unroll
    for (int k = 0; k < 4; k++) {
        const int e = e0 + k;
        const float* wr = Wq_w + (size_t)e * D_DIM;
        float s = 0.f;
        #pragma unroll
        for (int d = lane; d < D_DIM; d += 32) s += qs[d] * wr[d];
        #pragma unroll
        for (int o = 16; o; o >>= 1) s += __shfl_xor_sync(0xffffffffu, s, o);
        if (lane == 0) g_q[b * D_DIM + e] = s + Wq_b[e];
    }
}

// ---------------------------------------------------------------------------
// Helpers
// ---------------------------------------------------------------------------
__device__ __forceinline__ unsigned f2tf(float x) {
    unsigned u;
    asm("cvt.rna.tf32.f32 %0, %1;" : "=r"(u) : "f"(x));
    return u;
}
__device__ __forceinline__ void cp16(void* dst, const void* src) {
    unsigned s = (unsigned)__cvta_generic_to_shared(dst);
    asm volatile("cp.async.cg.shared.global [%0], [%1], 16;"
                 :: "r"(s), "l"(src) : "memory");
}
__device__ __forceinline__ float tanha(float x) {
    float y;
    asm("tanh.approx.f32 %0, %1;" : "=f"(y) : "f"(x));
    return y;
}

// dynamic smem layout (floats):
//   A: [2][128][LDA] = 9216 | B: [2][128][LDB] = 10240 (uint32)
//   q: 512 | v: 512 | bias: 512 | logits: 128  -> 21120 floats = 84480 B
#define SM_A(buf, r, c) sm[((buf) * BLK_S + (r)) * LDA + (c)]
#define SM_BW(buf, r, c) smw[((buf) * 128 + (r)) * LDB + (c)]
#define SM_Q(i) sm[19456 + (i)]
#define SM_V(i) sm[19968 + (i)]
#define SM_B(i) sm[20480 + (i)]
#define SM_L(i) sm[20992 + (i)]
#define SMW_OFF 9216
#define SMEM_FLOATS 21120

// ---------------------------------------------------------------------------
// Kernel 2: fused r-GEMM + tanh-logits + transposed store
// ---------------------------------------------------------------------------
__global__ void __launch_bounds__(NTHREADS, 2)
attn_main(const float* __restrict__ ref,
          const float* __restrict__ Wr_b,
          const float* __restrict__ value,
          float* __restrict__ out_r,
          float* __restrict__ out_logits)
{
    extern __shared__ float sm[];
    uint32_t* smw = reinterpret_cast<uint32_t*>(sm + SMW_OFF);
    const int tid    = threadIdx.x;
    const int lane   = tid & 31;
    const int warp   = tid >> 5;
    const int warp_s = warp & 3;   // 4 warps over S
    const int warp_e = warp >> 2;  // 2 warps over E
    const int b  = blockIdx.y;
    const int s0 = blockIdx.x * BLK_S;

    for (int i = tid; i < D_DIM; i += NTHREADS) {
        SM_Q(i) = g_q[b * D_DIM + i];
        SM_V(i) = value[i];
        SM_B(i) = Wr_b[i];
    }
    if (tid < BLK_S) SM_L(tid) = 0.0f;

    const float* aG = ref + ((size_t)b * S_DIM + s0) * D_DIM;
    float* outr_b = out_r + (size_t)b * D_DIM * S_DIM;

    for (int ei = 0; ei < 4; ei++) {
        const uint32_t* wG = g_wtf + (size_t)(ei * 128) * D_DIM;

        float acc[2][8][4];
        #pragma unroll
        for (int tm = 0; tm < 2; tm++)
            #pragma unroll
            for (int tn = 0; tn < 8; tn++)
                #pragma unroll
                for (int i = 0; i < 4; i++) acc[tm][tn][i] = 0.f;

        // prefetch k-tile 0 into buffer 0
        #pragma unroll
        for (int i = 0; i < 4; i++) {
            int v = tid + i * NTHREADS;        // 0..1023
            int row = v >> 3, c4 = (v & 7) * 4;
            cp16(&SM_A(0, row, c4), aG + (size_t)row * D_DIM + c4);
            cp16(&SM_BW(0, row, c4), wG + (size_t)row * D_DIM + c4);
        }
        asm volatile("cp.async.commit_group;" ::: "memory");

        #pragma unroll 1
        for (int kt = 0; kt < NK_TILES; kt++) {
            const int cur = kt & 1;
            if (kt + 1 < NK_TILES) {
                const int k0n = (kt + 1) * BLK_K;
                #pragma unroll
                for (int i = 0; i < 4; i++) {
                    int v = tid + i * NTHREADS;
                    int row = v >> 3, c4 = (v & 7) * 4;
                    cp16(&SM_A(cur ^ 1, row, c4), aG + (size_t)row * D_DIM + k0n + c4);
                    cp16(&SM_BW(cur ^ 1, row, c4), wG + (size_t)row * D_DIM + k0n + c4);
                }
                asm volatile("cp.async.commit_group;" ::: "memory");
                asm volatile("cp.async.wait_group 1;" ::: "memory");
            } else {
                asm volatile("cp.async.wait_group 0;" ::: "memory");
            }
            __syncthreads();

            #pragma unroll
            for (int ks = 0; ks < 4; ks++) {
                // ---- A fragments: 8 x LDS.32 + 8 x cvt ----
                const int ac = ks * 8 + (lane & 3);
                const int ar = warp_s * 32 + (lane >> 2);
                unsigned af[2][4];
                #pragma unroll
                for (int tm = 0; tm < 2; tm++) {
                    af[tm][0] = f2tf(SM_A(cur, ar + tm * 16,     ac));
                    af[tm][1] = f2tf(SM_A(cur, ar + tm * 16 + 8, ac));
                    af[tm][2] = f2tf(SM_A(cur, ar + tm * 16,     ac + 4));
                    af[tm][3] = f2tf(SM_A(cur, ar + tm * 16 + 8, ac + 4));
                }
                // ---- B fragments: 8 x LDS.64, pre-converted + pair-permuted ----
                const int br = warp_e * 64 + (lane >> 2);
                const int bc = ks * 8 + 2 * (lane & 3);   // {k, k+4} contiguous
                uint2 bf[8];
                #pragma unroll
                for (int tn = 0; tn < 8; tn++)
                    bf[tn] = *reinterpret_cast<const uint2*>(&SM_BW(cur, br + tn * 8, bc));
                #pragma unroll
                for (int tm = 0; tm < 2; tm++)
                    #pragma unroll
                    for (int tn = 0; tn < 8; tn++)
                        asm volatile(
                            "mma.sync.aligned.m16n8k8.row.col.f32.tf32.tf32.f32 "
                            "{%0,%1,%2,%3}, {%4,%5,%6,%7}, {%8,%9}, {%0,%1,%2,%3};"
                            : "+f"(acc[tm][tn][0]), "+f"(acc[tm][tn][1]),
                              "+f"(acc[tm][tn][2]), "+f"(acc[tm][tn][3])
                            : "r"(af[tm][0]), "r"(af[tm][1]),
                              "r"(af[tm][2]), "r"(af[tm][3]),
                              "r"(bf[tn].x), "r"(bf[tn].y));
            }
            __syncthreads();
        }

        // -------- epilogue for this 128-wide E block --------
        float lp[2][2] = {{0.f, 0.f}, {0.f, 0.f}};
        const int sg0 = s0 + warp_s * 32 + (lane >> 2);
        #pragma unroll
        for (int tm = 0; tm < 2; tm++) {
            const int srow = sg0 + tm * 16;
            #pragma unroll
            for (int tn = 0; tn < 8; tn++) {
                const int e = ei * 128 + warp_e * 64 + tn * 8 + 2 * (lane & 3);
                const float b0 = SM_B(e), b1 = SM_B(e + 1);
                const float r00 = acc[tm][tn][0] + b0;
                const float r01 = acc[tm][tn][1] + b1;
                const float r10 = acc[tm][tn][2] + b0;
                const float r11 = acc[tm][tn][3] + b1;
                outr_b[(size_t)e       * S_DIM + srow]     = r00;
                outr_b[(size_t)(e + 1) * S_DIM + srow]     = r01;
                outr_b[(size_t)e       * S_DIM + srow + 8] = r10;
                outr_b[(size_t)(e + 1) * S_DIM + srow + 8] = r11;
                const float q0 = SM_Q(e), q1 = SM_Q(e + 1);
                const float v0 = SM_V(e), v1 = SM_V(e + 1);
                lp[tm][0] += tanha(q0 + r00) * v0 + tanha(q1 + r01) * v1;
                lp[tm][1] += tanha(q0 + r10) * v0 + tanha(q1 + r11) * v1;
            }
        }
        #pragma unroll
        for (int tm = 0; tm < 2; tm++)
            #pragma unroll
            for (int h = 0; h < 2; h++) {
                float v = lp[tm][h];
                v += __shfl_xor_sync(0xffffffffu, v, 1);
                v += __shfl_xor_sync(0xffffffffu, v, 2);
                if ((lane & 3) == 0)
                    atomicAdd(&SM_L(warp_s * 32 + tm * 16 + h * 8 + (lane >> 2)), v);
            }
    }

    __syncthreads();
    if (tid < BLK_S)
        out_logits[(size_t)b * S_DIM + s0 + tid] = 10.0f * tanha(SM_L(tid));
}

// ---------------------------------------------------------------------------
// Launch
// ---------------------------------------------------------------------------
extern "C" void kernel_launch(void* const* d_in, const int* in_sizes, int n_in,
                              void* d_out, int out_size) {
    const float* query = (const float*)d_in[0];
    const float* ref   = (const float*)d_in[1];
    const float* Wq_w  = (const float*)d_in[2];
    const float* Wq_b  = (const float*)d_in[3];
    const float* Wr_w  = (const float*)d_in[4];
    const float* Wr_b  = (const float*)d_in[5];
    const float* value = (const float*)d_in[6];
    (void)in_sizes; (void)n_in; (void)out_size;

    float* out        = (float*)d_out;
    float* out_r      = out;                                   // [B, D, S]
    float* out_logits = out + (size_t)B_DIM * D_DIM * S_DIM;   // [B, S]

    wconv_kernel<<<256, 256>>>(Wr_w);
    qproj_kernel<<<dim3(B_DIM, 16), 256>>>(query, Wq_w, Wq_b);

    const size_t smem = SMEM_FLOATS * sizeof(float);
    cudaFuncSetAttribute(attn_main, cudaFuncAttributeMaxDynamicSharedMemorySize,
                         (int)smem);
    dim3 grid(S_DIM / BLK_S, B_DIM);
    attn_main<<<grid, NTHREADS, smem>>>(ref, Wr_b, value, out_r, out_logits);
}

// round 4
// speedup vs baseline: 1.4835x; 1.0752x over previous
#include <cuda_runtime.h>
#include <cstdint>
#include <math.h>

#define B_DIM 64
#define S_DIM 2048
#define D_DIM 512

#define BLK_S 128
#define BLK_K 32
#define LDA 36            // A pad: (36r + c) % 32 = 4r + c -> conflict-free 32-bit
#define LDB 40            // B pad: float2 stride 20 -> conflict-free 64-bit
#define NTHREADS 256
#define NK_TILES (D_DIM / BLK_K)   // 16

// scratch (no device mallocs allowed)
__device__ float    g_q[B_DIM * D_DIM];
__device__ uint32_t g_wtf[D_DIM * D_DIM];   // Wr_w as tf32 bits, k-permuted within 8-groups

// ---------------------------------------------------------------------------
// Kernel 0: fused prep. Blocks [0,256): Wr_w -> tf32 bits (k-pair permuted).
//           Blocks [256,1280): q = query @ Wq_w.T + Wq_b (warp-per-output).
// ---------------------------------------------------------------------------
__global__ void prep_kernel(const float* __restrict__ Wr_w,
                            const float* __restrict__ query,
                            const float* __restrict__ Wq_w,
                            const float* __restrict__ Wq_b) {
    if (blockIdx.x < 256) {
        int idx = blockIdx.x * 256 + threadIdx.x;
        #pragma unroll
        for (int it = 0; it < 4; it++, idx += 65536) {
            const int k = idx & 511;
            const int pos = (k & ~7) | ((k & 3) << 1) | ((k >> 2) & 1);
            unsigned u;
            asm("cvt.rna.tf32.f32 %0, %1;" : "=r"(u) : "f"(Wr_w[idx]));
            g_wtf[(idx & ~511) + pos] = u;
        }
    } else {
        __shared__ float qs[D_DIM];
        const int id2 = blockIdx.x - 256;         // 0..1023
        const int b = id2 & 63;
        const int eblk = id2 >> 6;                // 0..15
        const int tid = threadIdx.x, lane = tid & 31, w = tid >> 5;
        for (int i = tid; i < D_DIM; i += 256) qs[i] = query[(size_t)b * D_DIM + i];
        __syncthreads();
        const int e0 = eblk * 32 + w * 4;
        #pragma unroll
        for (int k = 0; k < 4; k++) {
            const int e = e0 + k;
            const float* wr = Wq_w + (size_t)e * D_DIM;
            float s = 0.f;
            #pragma unroll
            for (int d = lane; d < D_DIM; d += 32) s += qs[d] * wr[d];
            #pragma unroll
            for (int o = 16; o; o >>= 1) s += __shfl_xor_sync(0xffffffffu, s, o);
            if (lane == 0) g_q[b * D_DIM + e] = s + Wq_b[e];
        }
    }
}

// ---------------------------------------------------------------------------
// Helpers
// ---------------------------------------------------------------------------
__device__ __forceinline__ void cp16(void* dst, const void* src) {
    unsigned s = (unsigned)__cvta_generic_to_shared(dst);
    asm volatile("cp.async.cg.shared.global [%0], [%1], 16;"
                 :: "r"(s), "l"(src) : "memory");
}
__device__ __forceinline__ float tanha(float x) {
    float y;
    asm("tanh.approx.f32 %0, %1;" : "=f"(y) : "f"(x));
    return y;
}

// dynamic smem layout (floats):
//   A: [2][128][LDA] = 9216 | B: [2][128][LDB] = 10240 (uint32)
//   q: 512 | v: 512 | bias: 512 | logits: 128  -> 21120 floats = 84480 B
#define SM_A(buf, r, c) sm[((buf) * BLK_S + (r)) * LDA + (c)]
#define SM_BW(buf, r, c) smw[((buf) * 128 + (r)) * LDB + (c)]
#define SM_Q(i) sm[19456 + (i)]
#define SM_V(i) sm[19968 + (i)]
#define SM_B(i) sm[20480 + (i)]
#define SM_L(i) sm[20992 + (i)]
#define SMW_OFF 9216
#define SMEM_FLOATS 21120

// ---------------------------------------------------------------------------
// Kernel 1: fused r-GEMM + tanh-logits + transposed store
// ---------------------------------------------------------------------------
__global__ void __launch_bounds__(NTHREADS, 2)
attn_main(const float* __restrict__ ref,
          const float* __restrict__ Wr_b,
          const float* __restrict__ value,
          float* __restrict__ out_r,
          float* __restrict__ out_logits)
{
    extern __shared__ float sm[];
    uint32_t* smw = reinterpret_cast<uint32_t*>(sm + SMW_OFF);
    const int tid    = threadIdx.x;
    const int lane   = tid & 31;
    const int warp   = tid >> 5;
    const int warp_s = warp & 3;   // 4 warps over S
    const int warp_e = warp >> 2;  // 2 warps over E
    const int b  = blockIdx.y;
    const int s0 = blockIdx.x * BLK_S;

    for (int i = tid; i < D_DIM; i += NTHREADS) {
        SM_Q(i) = g_q[b * D_DIM + i];
        SM_V(i) = value[i];
        SM_B(i) = Wr_b[i];
    }
    if (tid < BLK_S) SM_L(tid) = 0.0f;

    const float* aG = ref + ((size_t)b * S_DIM + s0) * D_DIM;
    float* outr_b = out_r + (size_t)b * D_DIM * S_DIM;

    // fragment base indices (invariant)
    const int ar = warp_s * 32 + (lane >> 2);
    const int aq = lane & 3;
    const int br = warp_e * 64 + (lane >> 2);

    for (int ei = 0; ei < 4; ei++) {
        const uint32_t* wG = g_wtf + (size_t)(ei * 128) * D_DIM;

        float acc[2][8][4];
        #pragma unroll
        for (int tm = 0; tm < 2; tm++)
            #pragma unroll
            for (int tn = 0; tn < 8; tn++)
                #pragma unroll
                for (int i = 0; i < 4; i++) acc[tm][tn][i] = 0.f;

        // prefetch k-tile 0 into buffer 0
        #pragma unroll
        for (int i = 0; i < 4; i++) {
            int v = tid + i * NTHREADS;        // 0..1023
            int row = v >> 3, c4 = (v & 7) * 4;
            cp16(&SM_A(0, row, c4), aG + (size_t)row * D_DIM + c4);
            cp16(&SM_BW(0, row, c4), wG + (size_t)row * D_DIM + c4);
        }
        asm volatile("cp.async.commit_group;" ::: "memory");

        #pragma unroll 1
        for (int kt = 0; kt < NK_TILES; kt++) {
            const int cur = kt & 1;
            if (kt + 1 < NK_TILES) {
                const int k0n = (kt + 1) * BLK_K;
                #pragma unroll
                for (int i = 0; i < 4; i++) {
                    int v = tid + i * NTHREADS;
                    int row = v >> 3, c4 = (v & 7) * 4;
                    cp16(&SM_A(cur ^ 1, row, c4), aG + (size_t)row * D_DIM + k0n + c4);
                    cp16(&SM_BW(cur ^ 1, row, c4), wG + (size_t)row * D_DIM + k0n + c4);
                }
                asm volatile("cp.async.commit_group;" ::: "memory");
                asm volatile("cp.async.wait_group 1;" ::: "memory");
            } else {
                asm volatile("cp.async.wait_group 0;" ::: "memory");
            }
            __syncthreads();

            // ---- software-pipelined ks slices ----
            unsigned af[2][2][4];   // [buf][tm][frag], raw fp32 bits as tf32 (rz)
            uint2    bf[2][8];      // [buf][tn], pre-converted tf32 bits

            // load slice 0
            {
                const int ac = aq;
                #pragma unroll
                for (int tm = 0; tm < 2; tm++) {
                    af[0][tm][0] = __float_as_uint(SM_A(cur, ar + tm * 16,     ac));
                    af[0][tm][1] = __float_as_uint(SM_A(cur, ar + tm * 16 + 8, ac));
                    af[0][tm][2] = __float_as_uint(SM_A(cur, ar + tm * 16,     ac + 4));
                    af[0][tm][3] = __float_as_uint(SM_A(cur, ar + tm * 16 + 8, ac + 4));
                }
                const int bc = 2 * aq;
                #pragma unroll
                for (int tn = 0; tn < 8; tn++)
                    bf[0][tn] = *reinterpret_cast<const uint2*>(&SM_BW(cur, br + tn * 8, bc));
            }

            #pragma unroll
            for (int ks = 0; ks < 4; ks++) {
                const int pb = ks & 1;
                if (ks < 3) {
                    const int nb = pb ^ 1;
                    const int ac = (ks + 1) * 8 + aq;
                    #pragma unroll
                    for (int tm = 0; tm < 2; tm++) {
                        af[nb][tm][0] = __float_as_uint(SM_A(cur, ar + tm * 16,     ac));
                        af[nb][tm][1] = __float_as_uint(SM_A(cur, ar + tm * 16 + 8, ac));
                        af[nb][tm][2] = __float_as_uint(SM_A(cur, ar + tm * 16,     ac + 4));
                        af[nb][tm][3] = __float_as_uint(SM_A(cur, ar + tm * 16 + 8, ac + 4));
                    }
                    const int bc = (ks + 1) * 8 + 2 * aq;
                    #pragma unroll
                    for (int tn = 0; tn < 8; tn++)
                        bf[nb][tn] = *reinterpret_cast<const uint2*>(&SM_BW(cur, br + tn * 8, bc));
                }
                #pragma unroll
                for (int tm = 0; tm < 2; tm++)
                    #pragma unroll
                    for (int tn = 0; tn < 8; tn++)
                        asm volatile(
                            "mma.sync.aligned.m16n8k8.row.col.f32.tf32.tf32.f32 "
                            "{%0,%1,%2,%3}, {%4,%5,%6,%7}, {%8,%9}, {%0,%1,%2,%3};"
                            : "+f"(acc[tm][tn][0]), "+f"(acc[tm][tn][1]),
                              "+f"(acc[tm][tn][2]), "+f"(acc[tm][tn][3])
                            : "r"(af[pb][tm][0]), "r"(af[pb][tm][1]),
                              "r"(af[pb][tm][2]), "r"(af[pb][tm][3]),
                              "r"(bf[pb][tn].x), "r"(bf[pb][tn].y));
            }
            __syncthreads();
        }

        // -------- epilogue for this 128-wide E block --------
        float lp[2][2] = {{0.f, 0.f}, {0.f, 0.f}};
        const int sg0 = s0 + warp_s * 32 + (lane >> 2);
        #pragma unroll
        for (int tm = 0; tm < 2; tm++) {
            const int srow = sg0 + tm * 16;
            #pragma unroll
            for (int tn = 0; tn < 8; tn++) {
                const int e = ei * 128 + warp_e * 64 + tn * 8 + 2 * (lane & 3);
                const float b0 = SM_B(e), b1 = SM_B(e + 1);
                const float r00 = acc[tm][tn][0] + b0;
                const float r01 = acc[tm][tn][1] + b1;
                const float r10 = acc[tm][tn][2] + b0;
                const float r11 = acc[tm][tn][3] + b1;
                outr_b[(size_t)e       * S_DIM + srow]     = r00;
                outr_b[(size_t)(e + 1) * S_DIM + srow]     = r01;
                outr_b[(size_t)e       * S_DIM + srow + 8] = r10;
                outr_b[(size_t)(e + 1) * S_DIM + srow + 8] = r11;
                const float q0 = SM_Q(e), q1 = SM_Q(e + 1);
                const float v0 = SM_V(e), v1 = SM_V(e + 1);
                lp[tm][0] += tanha(q0 + r00) * v0 + tanha(q1 + r01) * v1;
                lp[tm][1] += tanha(q0 + r10) * v0 + tanha(q1 + r11) * v1;
            }
        }
        #pragma unroll
        for (int tm = 0; tm < 2; tm++)
            #pragma unroll
            for (int h = 0; h < 2; h++) {
                float v = lp[tm][h];
                v += __shfl_xor_sync(0xffffffffu, v, 1);
                v += __shfl_xor_sync(0xffffffffu, v, 2);
                if ((lane & 3) == 0)
                    atomicAdd(&SM_L(warp_s * 32 + tm * 16 + h * 8 + (lane >> 2)), v);
            }
    }

    __syncthreads();
    if (tid < BLK_S)
        out_logits[(size_t)b * S_DIM + s0 + tid] = 10.0f * tanha(SM_L(tid));
}

// ---------------------------------------------------------------------------
// Launch
// ---------------------------------------------------------------------------
extern "C" void kernel_launch(void* const* d_in, const int* in_sizes, int n_in,
                              void* d_out, int out_size) {
    const float* query = (const float*)d_in[0];
    const float* ref   = (const float*)d_in[1];
    const float* Wq_w  = (const float*)d_in[2];
    const float* Wq_b  = (const float*)d_in[3];
    const float* Wr_w  = (const float*)d_in[4];
    const float* Wr_b  = (const float*)d_in[5];
    const float* value = (const float*)d_in[6];
    (void)in_sizes; (void)n_in; (void)out_size;

    float* out        = (float*)d_out;
    float* out_r      = out;                                   // [B, D, S]
    float* out_logits = out + (size_t)B_DIM * D_DIM * S_DIM;   // [B, S]

    prep_kernel<<<1280, 256>>>(Wr_w, query, Wq_w, Wq_b);

    const size_t smem = SMEM_FLOATS * sizeof(float);
    cudaFuncSetAttribute(attn_main, cudaFuncAttributeMaxDynamicSharedMemorySize,
                         (int)smem);
    dim3 grid(S_DIM / BLK_S, B_DIM);
    attn_main<<<grid, NTHREADS, smem>>>(ref, Wr_b, value, out_r, out_logits);
}

// round 5
// speedup vs baseline: 1.6355x; 1.1025x over previous
#include <cuda_runtime.h>
#include <cstdint>
#include <math.h>

#define B_DIM 64
#define S_DIM 2048
#define D_DIM 512

#define BLK_S 128
#define NTHREADS 256
#define NMACRO 64            // 4 ei * 16 kt
#define NSTAGE 3
#define STG_WORDS 8192       // A 4096 + B 4096 floats per stage
#define CONST_OFF (NSTAGE * STG_WORDS)          // 24576
#define SMEM_WORDS (CONST_OFF + 1664)           // bias 512 + qpb 512 + v 512 + logits 128
// -> 104960 bytes, 2 CTAs/SM

// scratch (no device mallocs allowed)
__device__ float    g_qpb[B_DIM * D_DIM];        // q + Wq_b + Wr_b
__device__ uint32_t g_wtf[NMACRO * 4096];        // W as tf32 bits, fragment-ordered

// ---------------------------------------------------------------------------
// prep: blocks [0,256): W -> fragment-ordered tf32.  [256,1280): q projection.
// g_wtf flat index o = g*4096 + c*4 + w,  c = ((ks*2+we)*4 + j)*32 + lane
//   tn = (j*4+w)>>1, h = w&1
//   e  = ei*128 + we*64 + tn*8 + (lane>>2)
//   k  = kt*32 + ks*8 + (lane&3) + h*4        (g = ei*16 + kt)
// ---------------------------------------------------------------------------
__global__ void prep_kernel(const float* __restrict__ Wr_w,
                            const float* __restrict__ query,
                            const float* __restrict__ Wq_w,
                            const float* __restrict__ Wq_b,
                            const float* __restrict__ Wr_b) {
    if (blockIdx.x < 256) {
        int o = blockIdx.x * 256 + threadIdx.x;
        #pragma unroll
        for (int it = 0; it < 4; it++, o += 65536) {
            const int g = o >> 12, rem = o & 4095;
            const int c = rem >> 2, w = rem & 3;
            const int lane = c & 31, t = c >> 5;
            const int j = t & 3, we = (t >> 2) & 1, ks = t >> 3;
            const int ei = g >> 4, kt = g & 15;
            const int tn = (j * 4 + w) >> 1, h = w & 1;
            const int e = ei * 128 + we * 64 + tn * 8 + (lane >> 2);
            const int k = kt * 32 + ks * 8 + (lane & 3) + h * 4;
            unsigned u;
            asm("cvt.rna.tf32.f32 %0, %1;" : "=r"(u) : "f"(Wr_w[e * D_DIM + k]));
            g_wtf[o] = u;
        }
    } else {
        __shared__ float qs[D_DIM];
        const int id2 = blockIdx.x - 256;
        const int b = id2 & 63;
        const int eblk = id2 >> 6;
        const int tid = threadIdx.x, lane = tid & 31, w = tid >> 5;
        for (int i = tid; i < D_DIM; i += 256) qs[i] = query[(size_t)b * D_DIM + i];
        __syncthreads();
        const int e0 = eblk * 32 + w * 4;
        #pragma unroll
        for (int k = 0; k < 4; k++) {
            const int e = e0 + k;
            const float* wr = Wq_w + (size_t)e * D_DIM;
            float s = 0.f;
            #pragma unroll
            for (int d = lane; d < D_DIM; d += 32) s += qs[d] * wr[d];
            #pragma unroll
            for (int o = 16; o; o >>= 1) s += __shfl_xor_sync(0xffffffffu, s, o);
            if (lane == 0) g_qpb[b * D_DIM + e] = s + Wq_b[e] + Wr_b[e];
        }
    }
}

// ---------------------------------------------------------------------------
// helpers
// ---------------------------------------------------------------------------
__device__ __forceinline__ void cp16(void* dst, const void* src) {
    unsigned s = (unsigned)__cvta_generic_to_shared(dst);
    asm volatile("cp.async.cg.shared.global [%0], [%1], 16;"
                 :: "r"(s), "l"(src) : "memory");
}
__device__ __forceinline__ float tanha(float x) {
    float y;
    asm("tanh.approx.f32 %0, %1;" : "=f"(y) : "f"(x));
    return y;
}

#define SM_BIAS(i) sm[CONST_OFF + (i)]
#define SM_QPB(i)  sm[CONST_OFF + 512 + (i)]
#define SM_V(i)    sm[CONST_OFF + 1024 + (i)]
#define SM_L(i)    sm[CONST_OFF + 1536 + (i)]

// ---------------------------------------------------------------------------
// main: flattened 64-iteration, 3-stage cp.async ring, 1 sync per k-tile
// ---------------------------------------------------------------------------
__global__ void __launch_bounds__(NTHREADS, 2)
attn_main(const float* __restrict__ ref,
          const float* __restrict__ Wr_b,
          const float* __restrict__ value,
          float* __restrict__ out_r,
          float* __restrict__ out_logits)
{
    extern __shared__ float sm[];
    const int tid    = threadIdx.x;
    const int lane   = tid & 31;
    const int warp   = tid >> 5;
    const int warp_s = warp & 3;
    const int warp_e = warp >> 2;
    const int b  = blockIdx.y;
    const int s0 = blockIdx.x * BLK_S;

    const float* aG = ref + ((size_t)b * S_DIM + s0) * D_DIM;
    float* outr_b = out_r + (size_t)b * D_DIM * S_DIM;

    // per-thread invariant chunk coords for A prefetch
    // chunk ca = tid + i*256: row = ca>>3, c4 = (ca&7)*4
    // A dst word = row*32 + (((ca&7) ^ (row&7))<<2)

    // ---- prefetch stages 0 and 1 ----
    #pragma unroll
    for (int gp = 0; gp < 2; gp++) {
        float* sa = sm + gp * STG_WORDS;
        uint32_t* sb = reinterpret_cast<uint32_t*>(sm) + gp * STG_WORDS + 4096;
        const float* asrc = aG + (gp & 15) * 32;
        const uint32_t* bsrc = g_wtf + (size_t)gp * 4096;
        #pragma unroll
        for (int i = 0; i < 4; i++) {
            const int ca = tid + i * 256;
            const int row = ca >> 3, cg = ca & 7;
            cp16(sa + row * 32 + ((cg ^ (row & 7)) << 2),
                 asrc + (size_t)row * D_DIM + cg * 4);
            cp16(sb + ca * 4, bsrc + ca * 4);
        }
        asm volatile("cp.async.commit_group;" ::: "memory");
    }

    // epilogue constants
    for (int i = tid; i < D_DIM; i += NTHREADS) {
        SM_BIAS(i) = Wr_b[i];
        SM_QPB(i)  = g_qpb[b * D_DIM + i];
        SM_V(i)    = value[i];
    }
    if (tid < BLK_S) SM_L(tid) = 0.0f;

    // fragment invariants
    const int ar  = warp_s * 32 + (lane >> 2);  // A row base
    const int aq  = lane & 3;
    const int sg0b = lane >> 2;                 // A swizzle group base (= row&7)
    const int bbase = warp_e * 4 * 128 + lane * 4; // B word base within ks block

    float acc[2][8][4];
    #pragma unroll
    for (int tm = 0; tm < 2; tm++)
        #pragma unroll
        for (int tn = 0; tn < 8; tn++)
            #pragma unroll
            for (int i = 0; i < 4; i++) acc[tm][tn][i] = 0.f;

    unsigned af[2][2][4];
    uint4    bq[2][4];

    #pragma unroll 1
    for (int g = 0; g < NMACRO; g++) {
        if (g == NMACRO - 1)
            asm volatile("cp.async.wait_group 0;" ::: "memory");
        else
            asm volatile("cp.async.wait_group 1;" ::: "memory");
        __syncthreads();

        // prefetch stage g+2
        if (g + 2 < NMACRO) {
            const int gp = g + 2;
            const int slot = gp % NSTAGE;
            float* sa = sm + slot * STG_WORDS;
            uint32_t* sb = reinterpret_cast<uint32_t*>(sm) + slot * STG_WORDS + 4096;
            const float* asrc = aG + (gp & 15) * 32;
            const uint32_t* bsrc = g_wtf + (size_t)gp * 4096;
            #pragma unroll
            for (int i = 0; i < 4; i++) {
                const int ca = tid + i * 256;
                const int row = ca >> 3, cg = ca & 7;
                cp16(sa + row * 32 + ((cg ^ (row & 7)) << 2),
                     asrc + (size_t)row * D_DIM + cg * 4);
                cp16(sb + ca * 4, bsrc + ca * 4);
            }
            asm volatile("cp.async.commit_group;" ::: "memory");
        }

        const int slot = g % NSTAGE;
        const float* sa = sm + slot * STG_WORDS;
        const uint32_t* sb = reinterpret_cast<const uint32_t*>(sm) + slot * STG_WORDS + 4096;

        // load slice 0 fragments into buffer 0
        {
            #pragma unroll
            for (int tm = 0; tm < 2; tm++) {
                const int r0 = ar + tm * 16;
                af[0][tm][0] = __float_as_uint(sa[ r0      * 32 + ((0 ^ sg0b) << 2) + aq]);
                af[0][tm][1] = __float_as_uint(sa[(r0 + 8) * 32 + ((0 ^ sg0b) << 2) + aq]);
                af[0][tm][2] = __float_as_uint(sa[ r0      * 32 + ((1 ^ sg0b) << 2) + aq]);
                af[0][tm][3] = __float_as_uint(sa[(r0 + 8) * 32 + ((1 ^ sg0b) << 2) + aq]);
            }
            #pragma unroll
            for (int j = 0; j < 4; j++)
                bq[0][j] = *reinterpret_cast<const uint4*>(sb + bbase + j * 128);
        }

        #pragma unroll
        for (int ks = 0; ks < 4; ks++) {
            const int pb = ks & 1;
            if (ks < 3) {
                const int nb = pb ^ 1;
                const int g0 = (ks + 1) * 2;
                #pragma unroll
                for (int tm = 0; tm < 2; tm++) {
                    const int r0 = ar + tm * 16;
                    af[nb][tm][0] = __float_as_uint(sa[ r0      * 32 + (((g0    ) ^ sg0b) << 2) + aq]);
                    af[nb][tm][1] = __float_as_uint(sa[(r0 + 8) * 32 + (((g0    ) ^ sg0b) << 2) + aq]);
                    af[nb][tm][2] = __float_as_uint(sa[ r0      * 32 + (((g0 + 1) ^ sg0b) << 2) + aq]);
                    af[nb][tm][3] = __float_as_uint(sa[(r0 + 8) * 32 + (((g0 + 1) ^ sg0b) << 2) + aq]);
                }
                const uint32_t* sbk = sb + (ks + 1) * 1024 + bbase;
                #pragma unroll
                for (int j = 0; j < 4; j++)
                    bq[nb][j] = *reinterpret_cast<const uint4*>(sbk + j * 128);
            }
            #pragma unroll
            for (int tm = 0; tm < 2; tm++)
                #pragma unroll
                for (int tn = 0; tn < 8; tn++) {
                    const unsigned b0 = (tn & 1) ? bq[pb][tn >> 1].z : bq[pb][tn >> 1].x;
                    const unsigned b1 = (tn & 1) ? bq[pb][tn >> 1].w : bq[pb][tn >> 1].y;
                    asm volatile(
                        "mma.sync.aligned.m16n8k8.row.col.f32.tf32.tf32.f32 "
                        "{%0,%1,%2,%3}, {%4,%5,%6,%7}, {%8,%9}, {%0,%1,%2,%3};"
                        : "+f"(acc[tm][tn][0]), "+f"(acc[tm][tn][1]),
                          "+f"(acc[tm][tn][2]), "+f"(acc[tm][tn][3])
                        : "r"(af[pb][tm][0]), "r"(af[pb][tm][1]),
                          "r"(af[pb][tm][2]), "r"(af[pb][tm][3]),
                          "r"(b0), "r"(b1));
                }
        }

        // -------- epilogue at each ei boundary (overlaps with prefetches) ----
        if ((g & 15) == 15) {
            const int ei = g >> 4;
            float lp[2][2] = {{0.f, 0.f}, {0.f, 0.f}};
            const int sg0 = s0 + warp_s * 32 + (lane >> 2);
            #pragma unroll
            for (int tm = 0; tm < 2; tm++) {
                const int srow = sg0 + tm * 16;
                #pragma unroll
                for (int tn = 0; tn < 8; tn++) {
                    const int e = ei * 128 + warp_e * 64 + tn * 8 + 2 * (lane & 3);
                    const float b0 = SM_BIAS(e), b1 = SM_BIAS(e + 1);
                    const float a0 = acc[tm][tn][0], a1 = acc[tm][tn][1];
                    const float a2 = acc[tm][tn][2], a3 = acc[tm][tn][3];
                    outr_b[(size_t)e       * S_DIM + srow]     = a0 + b0;
                    outr_b[(size_t)(e + 1) * S_DIM + srow]     = a1 + b1;
                    outr_b[(size_t)e       * S_DIM + srow + 8] = a2 + b0;
                    outr_b[(size_t)(e + 1) * S_DIM + srow + 8] = a3 + b1;
                    const float q0 = SM_QPB(e), q1 = SM_QPB(e + 1);
                    const float v0 = SM_V(e), v1 = SM_V(e + 1);
                    lp[tm][0] += tanha(q0 + a0) * v0 + tanha(q1 + a1) * v1;
                    lp[tm][1] += tanha(q0 + a2) * v0 + tanha(q1 + a3) * v1;
                    acc[tm][tn][0] = 0.f; acc[tm][tn][1] = 0.f;
                    acc[tm][tn][2] = 0.f; acc[tm][tn][3] = 0.f;
                }
            }
            #pragma unroll
            for (int tm = 0; tm < 2; tm++)
                #pragma unroll
                for (int h = 0; h < 2; h++) {
                    float v = lp[tm][h];
                    v += __shfl_xor_sync(0xffffffffu, v, 1);
                    v += __shfl_xor_sync(0xffffffffu, v, 2);
                    if ((lane & 3) == 0)
                        atomicAdd(&SM_L(warp_s * 32 + tm * 16 + h * 8 + (lane >> 2)), v);
                }
        }
    }

    __syncthreads();
    if (tid < BLK_S)
        out_logits[(size_t)b * S_DIM + s0 + tid] = 10.0f * tanha(SM_L(tid));
}

// ---------------------------------------------------------------------------
// launch
// ---------------------------------------------------------------------------
extern "C" void kernel_launch(void* const* d_in, const int* in_sizes, int n_in,
                              void* d_out, int out_size) {
    const float* query = (const float*)d_in[0];
    const float* ref   = (const float*)d_in[1];
    const float* Wq_w  = (const float*)d_in[2];
    const float* Wq_b  = (const float*)d_in[3];
    const float* Wr_w  = (const float*)d_in[4];
    const float* Wr_b  = (const float*)d_in[5];
    const float* value = (const float*)d_in[6];
    (void)in_sizes; (void)n_in; (void)out_size;

    float* out        = (float*)d_out;
    float* out_r      = out;                                   // [B, D, S]
    float* out_logits = out + (size_t)B_DIM * D_DIM * S_DIM;   // [B, S]

    prep_kernel<<<1280, 256>>>(Wr_w, query, Wq_w, Wq_b, Wr_b);

    const size_t smem = SMEM_WORDS * sizeof(float);
    cudaFuncSetAttribute(attn_main, cudaFuncAttributeMaxDynamicSharedMemorySize,
                         (int)smem);
    dim3 grid(S_DIM / BLK_S, B_DIM);
    attn_main<<<grid, NTHREADS, smem>>>(ref, Wr_b, value, out_r, out_logits);
}

// round 6
// speedup vs baseline: 2.3565x; 1.4408x over previous
#include <cuda_runtime.h>
#include <cuda_fp16.h>
#include <cstdint>
#include <math.h>

#define B_DIM 64
#define S_DIM 2048
#define D_DIM 512

#define BLK_S 128
#define NTHREADS 256
#define NMACRO 32            // 4 ei * 8 kt (k-tile = 64)
#define NSTAGE 3
#define STG_WORDS 8192       // A 4096 words (8192 fp16) + B 4096 words
#define CONST_OFF (NSTAGE * STG_WORDS)          // 24576
#define SMEM_WORDS (CONST_OFF + 1664)           // 104960 B -> 2 CTAs/SM

// scratch (no device mallocs; __device__ globals are the sanctioned path)
__device__ __half   g_ref16[(size_t)B_DIM * S_DIM * D_DIM];   // 134 MB fp16 copy of ref
__device__ uint32_t g_w16[NMACRO * 4096];                     // W fp16, fragment-ordered
__device__ float    g_qpb[B_DIM * D_DIM];                     // q + Wq_b + Wr_b

// ---------------------------------------------------------------------------
// prep: [0,256): W -> fragment-ordered fp16 pairs
//       [256,1280): q projection
//       [1280,66816): ref fp32 -> fp16 (vectorized)
// ---------------------------------------------------------------------------
__global__ void prep_kernel(const float* __restrict__ Wr_w,
                            const float* __restrict__ query,
                            const float* __restrict__ Wq_w,
                            const float* __restrict__ Wq_b,
                            const float* __restrict__ Wr_b,
                            const float* __restrict__ ref) {
    if (blockIdx.x < 256) {
        int o = blockIdx.x * 256 + threadIdx.x;
        #pragma unroll
        for (int it = 0; it < 2; it++, o += 65536) {
            const int g = o >> 12, rem = o & 4095;
            const int c = rem >> 2, w = rem & 3;
            const int lane = c & 31, t = c >> 5;
            const int j = t & 3, we = (t >> 2) & 1, ks = t >> 3;
            const int ei = g >> 3, kt = g & 7;
            const int tn = j * 2 + (w >> 1);
            const int e = ei * 128 + we * 64 + tn * 8 + (lane >> 2);
            const int k = kt * 64 + ks * 16 + 2 * (lane & 3) + (w & 1) * 8;
            __half2 h = __floats2half2_rn(Wr_w[e * D_DIM + k], Wr_w[e * D_DIM + k + 1]);
            g_w16[o] = *reinterpret_cast<uint32_t*>(&h);
        }
    } else if (blockIdx.x < 1280) {
        __shared__ float qs[D_DIM];
        const int id2 = blockIdx.x - 256;
        const int b = id2 & 63;
        const int eblk = id2 >> 6;
        const int tid = threadIdx.x, lane = tid & 31, w = tid >> 5;
        for (int i = tid; i < D_DIM; i += 256) qs[i] = query[(size_t)b * D_DIM + i];
        __syncthreads();
        const int e0 = eblk * 32 + w * 4;
        #pragma unroll
        for (int k = 0; k < 4; k++) {
            const int e = e0 + k;
            const float* wr = Wq_w + (size_t)e * D_DIM;
            float s = 0.f;
            #pragma unroll
            for (int d = lane; d < D_DIM; d += 32) s += qs[d] * wr[d];
            #pragma unroll
            for (int o = 16; o; o >>= 1) s += __shfl_xor_sync(0xffffffffu, s, o);
            if (lane == 0) g_qpb[b * D_DIM + e] = s + Wq_b[e] + Wr_b[e];
        }
    } else {
        const size_t i4 = (size_t)(blockIdx.x - 1280) * 256 + threadIdx.x; // float4 idx
        const float4 v = reinterpret_cast<const float4*>(ref)[i4];
        __half2 h0 = __floats2half2_rn(v.x, v.y);
        __half2 h1 = __floats2half2_rn(v.z, v.w);
        uint2 o;
        o.x = *reinterpret_cast<uint32_t*>(&h0);
        o.y = *reinterpret_cast<uint32_t*>(&h1);
        reinterpret_cast<uint2*>(g_ref16)[i4] = o;
    }
}

// ---------------------------------------------------------------------------
// helpers
// ---------------------------------------------------------------------------
__device__ __forceinline__ void cp16(void* dst, const void* src) {
    unsigned s = (unsigned)__cvta_generic_to_shared(dst);
    asm volatile("cp.async.cg.shared.global [%0], [%1], 16;"
                 :: "r"(s), "l"(src) : "memory");
}
__device__ __forceinline__ float tanha(float x) {
    float y;
    asm("tanh.approx.f32 %0, %1;" : "=f"(y) : "f"(x));
    return y;
}
__device__ __forceinline__ void ldm4(unsigned& r0, unsigned& r1, unsigned& r2,
                                     unsigned& r3, unsigned addr) {
    asm volatile("ldmatrix.sync.aligned.m8n8.x4.shared.b16 {%0,%1,%2,%3}, [%4];"
                 : "=r"(r0), "=r"(r1), "=r"(r2), "=r"(r3) : "r"(addr));
}

#define SM_BIAS(i) sm[CONST_OFF + (i)]
#define SM_QPB(i)  sm[CONST_OFF + 512 + (i)]
#define SM_V(i)    sm[CONST_OFF + 1024 + (i)]
#define SM_L(i)    sm[CONST_OFF + 1536 + (i)]

// ---------------------------------------------------------------------------
// main: fp16 m16n8k16 HMMA, flattened 32-iteration, 3-stage cp.async ring
// ---------------------------------------------------------------------------
__global__ void __launch_bounds__(NTHREADS, 2)
attn_main(const float* __restrict__ Wr_b,
          const float* __restrict__ value,
          float* __restrict__ out_r,
          float* __restrict__ out_logits)
{
    extern __shared__ float sm[];
    const int tid    = threadIdx.x;
    const int lane   = tid & 31;
    const int warp   = tid >> 5;
    const int warp_s = warp & 3;
    const int warp_e = warp >> 2;
    const int b  = blockIdx.y;
    const int s0 = blockIdx.x * BLK_S;

    const __half* aG = g_ref16 + ((size_t)b * S_DIM + s0) * D_DIM;
    float* outr_b = out_r + (size_t)b * D_DIM * S_DIM;

    // ---- prefetch stages 0 and 1 ----
    #pragma unroll
    for (int gp = 0; gp < 2; gp++) {
        __half* sa = reinterpret_cast<__half*>(sm + gp * STG_WORDS);
        uint32_t* sb = reinterpret_cast<uint32_t*>(sm) + gp * STG_WORDS + 4096;
        const __half* asrc = aG + (gp & 7) * 64;
        const uint32_t* bsrc = g_w16 + (size_t)gp * 4096;
        #pragma unroll
        for (int i = 0; i < 4; i++) {
            const int ca = tid + i * 256;
            const int row = ca >> 3, gc = ca & 7;
            cp16(sa + row * 64 + ((gc ^ (row & 7)) << 3),
                 asrc + (size_t)row * D_DIM + gc * 8);
            cp16(sb + ca * 4, bsrc + ca * 4);
        }
        asm volatile("cp.async.commit_group;" ::: "memory");
    }

    // epilogue constants
    for (int i = tid; i < D_DIM; i += NTHREADS) {
        SM_BIAS(i) = Wr_b[i];
        SM_QPB(i)  = g_qpb[b * D_DIM + i];
        SM_V(i)    = value[i];
    }
    if (tid < BLK_S) SM_L(tid) = 0.0f;

    // ldmatrix per-thread row/granule selectors (invariant)
    const int lrow  = (lane & 15);        // row within 16-row tile
    const int lgsel = (lane >> 4) & 1;    // upper/lower k granule

    float acc[2][8][4];
    #pragma unroll
    for (int tm = 0; tm < 2; tm++)
        #pragma unroll
        for (int tn = 0; tn < 8; tn++)
            #pragma unroll
            for (int i = 0; i < 4; i++) acc[tm][tn][i] = 0.f;

    unsigned af[2][2][4];   // [buf][tm][reg]
    uint4    bq[4];         // single-buffered B fragments

    #pragma unroll 1
    for (int g = 0; g < NMACRO; g++) {
        if (g == NMACRO - 1)
            asm volatile("cp.async.wait_group 0;" ::: "memory");
        else
            asm volatile("cp.async.wait_group 1;" ::: "memory");
        __syncthreads();

        // prefetch stage g+2
        if (g + 2 < NMACRO) {
            const int gp = g + 2;
            const int slot = gp % NSTAGE;
            __half* sa = reinterpret_cast<__half*>(sm + slot * STG_WORDS);
            uint32_t* sb = reinterpret_cast<uint32_t*>(sm) + slot * STG_WORDS + 4096;
            const __half* asrc = aG + (gp & 7) * 64;
            const uint32_t* bsrc = g_w16 + (size_t)gp * 4096;
            #pragma unroll
            for (int i = 0; i < 4; i++) {
                const int ca = tid + i * 256;
                const int row = ca >> 3, gc = ca & 7;
                cp16(sa + row * 64 + ((gc ^ (row & 7)) << 3),
                     asrc + (size_t)row * D_DIM + gc * 8);
                cp16(sb + ca * 4, bsrc + ca * 4);
            }
            asm volatile("cp.async.commit_group;" ::: "memory");
        }

        const int slot = g % NSTAGE;
        const unsigned saddr =
            (unsigned)__cvta_generic_to_shared(sm + slot * STG_WORDS);
        const uint32_t* sb =
            reinterpret_cast<const uint32_t*>(sm) + slot * STG_WORDS + 4096;

        // ldmatrix slice 0 (ks=0) into buffer 0
        #pragma unroll
        for (int tm = 0; tm < 2; tm++) {
            const int r = warp_s * 32 + tm * 16 + lrow;
            const unsigned a = saddr + ((r * 8 + (lgsel ^ (r & 7))) << 4);
            ldm4(af[0][tm][0], af[0][tm][1], af[0][tm][2], af[0][tm][3], a);
        }

        #pragma unroll
        for (int ks = 0; ks < 4; ks++) {
            const int pb = ks & 1;
            // B fragments for this slice (single buffer)
            const uint32_t* sbk = sb + ks * 1024 + warp_e * 512 + lane * 4;
            #pragma unroll
            for (int j = 0; j < 4; j++)
                bq[j] = *reinterpret_cast<const uint4*>(sbk + j * 128);
            // A fragments for next slice
            if (ks < 3) {
                const int nb = pb ^ 1;
                const int gc = (ks + 1) * 2 + lgsel;
                #pragma unroll
                for (int tm = 0; tm < 2; tm++) {
                    const int r = warp_s * 32 + tm * 16 + lrow;
                    const unsigned a = saddr + ((r * 8 + (gc ^ (r & 7))) << 4);
                    ldm4(af[nb][tm][0], af[nb][tm][1], af[nb][tm][2], af[nb][tm][3], a);
                }
            }
            #pragma unroll
            for (int tm = 0; tm < 2; tm++)
                #pragma unroll
                for (int tn = 0; tn < 8; tn++) {
                    const unsigned b0 = (tn & 1) ? bq[tn >> 1].z : bq[tn >> 1].x;
                    const unsigned b1 = (tn & 1) ? bq[tn >> 1].w : bq[tn >> 1].y;
                    asm volatile(
                        "mma.sync.aligned.m16n8k16.row.col.f32.f16.f16.f32 "
                        "{%0,%1,%2,%3}, {%4,%5,%6,%7}, {%8,%9}, {%0,%1,%2,%3};"
                        : "+f"(acc[tm][tn][0]), "+f"(acc[tm][tn][1]),
                          "+f"(acc[tm][tn][2]), "+f"(acc[tm][tn][3])
                        : "r"(af[pb][tm][0]), "r"(af[pb][tm][1]),
                          "r"(af[pb][tm][2]), "r"(af[pb][tm][3]),
                          "r"(b0), "r"(b1));
                }
        }

        // -------- epilogue at each ei boundary --------
        if ((g & 7) == 7) {
            const int ei = g >> 3;
            float lp[2][2] = {{0.f, 0.f}, {0.f, 0.f}};
            const int sg0 = s0 + warp_s * 32 + (lane >> 2);
            #pragma unroll
            for (int tm = 0; tm < 2; tm++) {
                const int srow = sg0 + tm * 16;
                #pragma unroll
                for (int tn = 0; tn < 8; tn++) {
                    const int e = ei * 128 + warp_e * 64 + tn * 8 + 2 * (lane & 3);
                    const float b0 = SM_BIAS(e), b1 = SM_BIAS(e + 1);
                    const float a0 = acc[tm][tn][0], a1 = acc[tm][tn][1];
                    const float a2 = acc[tm][tn][2], a3 = acc[tm][tn][3];
                    outr_b[(size_t)e       * S_DIM + srow]     = a0 + b0;
                    outr_b[(size_t)(e + 1) * S_DIM + srow]     = a1 + b1;
                    outr_b[(size_t)e       * S_DIM + srow + 8] = a2 + b0;
                    outr_b[(size_t)(e + 1) * S_DIM + srow + 8] = a3 + b1;
                    const float q0 = SM_QPB(e), q1 = SM_QPB(e + 1);
                    const float v0 = SM_V(e), v1 = SM_V(e + 1);
                    lp[tm][0] += tanha(q0 + a0) * v0 + tanha(q1 + a1) * v1;
                    lp[tm][1] += tanha(q0 + a2) * v0 + tanha(q1 + a3) * v1;
                    acc[tm][tn][0] = 0.f; acc[tm][tn][1] = 0.f;
                    acc[tm][tn][2] = 0.f; acc[tm][tn][3] = 0.f;
                }
            }
            #pragma unroll
            for (int tm = 0; tm < 2; tm++)
                #pragma unroll
                for (int h = 0; h < 2; h++) {
                    float v = lp[tm][h];
                    v += __shfl_xor_sync(0xffffffffu, v, 1);
                    v += __shfl_xor_sync(0xffffffffu, v, 2);
                    if ((lane & 3) == 0)
                        atomicAdd(&SM_L(warp_s * 32 + tm * 16 + h * 8 + (lane >> 2)), v);
                }
        }
    }

    __syncthreads();
    if (tid < BLK_S)
        out_logits[(size_t)b * S_DIM + s0 + tid] = 10.0f * tanha(SM_L(tid));
}

// ---------------------------------------------------------------------------
// launch
// ---------------------------------------------------------------------------
extern "C" void kernel_launch(void* const* d_in, const int* in_sizes, int n_in,
                              void* d_out, int out_size) {
    const float* query = (const float*)d_in[0];
    const float* ref   = (const float*)d_in[1];
    const float* Wq_w  = (const float*)d_in[2];
    const float* Wq_b  = (const float*)d_in[3];
    const float* Wr_w  = (const float*)d_in[4];
    const float* Wr_b  = (const float*)d_in[5];
    const float* value = (const float*)d_in[6];
    (void)in_sizes; (void)n_in; (void)out_size;

    float* out        = (float*)d_out;
    float* out_r      = out;                                   // [B, D, S]
    float* out_logits = out + (size_t)B_DIM * D_DIM * S_DIM;   // [B, S]

    prep_kernel<<<66816, 256>>>(Wr_w, query, Wq_w, Wq_b, Wr_b, ref);

    const size_t smem = SMEM_WORDS * sizeof(float);
    cudaFuncSetAttribute(attn_main, cudaFuncAttributeMaxDynamicSharedMemorySize,
                         (int)smem);
    dim3 grid(S_DIM / BLK_S, B_DIM);
    attn_main<<<grid, NTHREADS, smem>>>(Wr_b, value, out_r, out_logits);
}